// round 13
// baseline (speedup 1.0000x reference)
#include <cuda_runtime.h>
#include <cstdint>

#define N_NODES 50000
#define N_EDGES 800000
#define DIM     64
#define N_REL   16

// ---------------- scratch (device globals: allocation-free) ----------------
__device__ float g_proj[(size_t)N_REL * N_NODES * DIM];  // 204.8 MB
__device__ float g_denom[N_NODES];
__device__ int   g_cnt16[16];
__device__ int   g_off16[17];     // immutable chunk boundaries
__device__ int   g_pos16[16];     // scatter cursor
__device__ int4  g_sed[N_EDGES];  // sorted (src, dst, eid, etype)

// ---------------- helpers ----------------
__device__ __forceinline__ float fast_tanh(float x) {
    float xc = fminf(fmaxf(x, -15.f), 15.f);
    float t  = __expf(2.f * xc);
    return __fdividef(t - 1.f, t + 1.f);
}
__device__ __forceinline__ unsigned long long pack2(float x) {
    unsigned long long r;
    asm("mov.b64 %0, {%1, %1};" : "=l"(r) : "f"(x));
    return r;
}
__device__ __forceinline__ void ffma2(unsigned long long& d,
                                      unsigned long long a,
                                      unsigned long long b) {
    asm("fma.rn.f32x2 %0, %1, %2, %0;" : "+l"(d) : "l"(a), "l"(b));
}
__device__ __forceinline__ void unpack2(unsigned long long v, float& lo, float& hi) {
    asm("mov.b64 {%0, %1}, %2;" : "=f"(lo), "=f"(hi) : "l"(v));
}
__device__ __forceinline__ float leaky(float x) { return x >= 0.f ? x : 0.01f * x; }

// ---------------- init: zero hnb + denom + sort counters ----------------
__global__ void init_kernel(float* __restrict__ hnb) {
    int i = blockIdx.x * blockDim.x + threadIdx.x;
    if (i < N_NODES * DIM / 4) ((float4*)hnb)[i] = make_float4(0.f, 0.f, 0.f, 0.f);
    if (i < N_NODES) g_denom[i] = 0.f;
    if (i < 16) g_cnt16[i] = 0;
}

// ---------------- sort by etype (stream B; R3-proven machinery) ----------
__global__ void hist16_kernel(const int* __restrict__ etype) {
    __shared__ int lh[16];
    if (threadIdx.x < 16) lh[threadIdx.x] = 0;
    __syncthreads();
    for (int e = blockIdx.x * blockDim.x + threadIdx.x; e < N_EDGES;
         e += gridDim.x * blockDim.x)
        atomicAdd(&lh[etype[e]], 1);
    __syncthreads();
    if (threadIdx.x < 16) atomicAdd(&g_cnt16[threadIdx.x], lh[threadIdx.x]);
}

__global__ void scan16_kernel() {
    if (threadIdx.x == 0 && blockIdx.x == 0) {
        int off = 0;
        for (int t = 0; t < 16; t++) { g_off16[t] = off; g_pos16[t] = off; off += g_cnt16[t]; }
        g_off16[16] = off;
    }
}

__global__ void scatter16_kernel(const int* __restrict__ src,
                                 const int* __restrict__ dst,
                                 const int* __restrict__ etype) {
    __shared__ int lh[16], lbase[16];
    int e = blockIdx.x * 256 + threadIdx.x;
    if (threadIdx.x < 16) lh[threadIdx.x] = 0;
    __syncthreads();
    int t = 0, rk = 0;
    bool valid = (e < N_EDGES);
    if (valid) { t = etype[e]; rk = atomicAdd(&lh[t], 1); }
    __syncthreads();
    if (threadIdx.x < 16 && lh[threadIdx.x] > 0)
        lbase[threadIdx.x] = atomicAdd(&g_pos16[threadIdx.x], lh[threadIdx.x]);
    __syncthreads();
    if (valid) g_sed[lbase[t] + rk] = make_int4(src[e], dst[e], e, t);
}

// ---------------- proj (EXACT R8 config — proven 10.7us/rel) --------------
#define PROJ_TN 192
__global__ void __launch_bounds__(256, 3) proj_kernel(const float* __restrict__ nfeat,
                                                      const float* __restrict__ relW,
                                                      int r_base) {
    __shared__ __align__(16) float Ws[64 * 64];          // 16 KB [d][col]
    __shared__ __align__(16) float Xs[64 * PROJ_TN];     // 48 KB transposed [d][node]

    const int r   = r_base + blockIdx.y;
    const int n0  = blockIdx.x * PROJ_TN;
    const int tid = threadIdx.x;

    {
        const float4* wsrc = (const float4*)(relW + (size_t)r * 4096);
        float4* wdst = (float4*)Ws;
        #pragma unroll
        for (int i = tid; i < 1024; i += 256) wdst[i] = wsrc[i];
    }
    if (tid < PROJ_TN) {
        int n = n0 + tid;
        if (n < N_NODES) {
            const float4* nr = (const float4*)(nfeat + (size_t)n * DIM);
            #pragma unroll
            for (int c4 = 0; c4 < 16; c4++) {
                float4 v = nr[c4];
                Xs[(c4 * 4 + 0) * PROJ_TN + tid] = v.x;
                Xs[(c4 * 4 + 1) * PROJ_TN + tid] = v.y;
                Xs[(c4 * 4 + 2) * PROJ_TN + tid] = v.z;
                Xs[(c4 * 4 + 3) * PROJ_TN + tid] = v.w;
            }
        } else {
            #pragma unroll
            for (int c = 0; c < 64; c++) Xs[c * PROJ_TN + tid] = 0.f;
        }
    }
    __syncthreads();

    const int cg = tid & 7;
    const int tr = tid >> 3;
    const float* wbase = Ws + cg * 2;      // + d*64 + 16*j
    const float* xbase = Xs + tr * 6;      // + d*PROJ_TN + m

    unsigned long long acc[6][4];
    #pragma unroll
    for (int m = 0; m < 6; m++)
        #pragma unroll
        for (int j = 0; j < 4; j++) acc[m][j] = 0ull;

    #pragma unroll 4
    for (int d = 0; d < 64; d++) {
        unsigned long long w2[4];
        #pragma unroll
        for (int j = 0; j < 4; j++)
            w2[j] = *(const unsigned long long*)(wbase + d * 64 + 16 * j);
        #pragma unroll
        for (int m = 0; m < 6; m++) {
            unsigned long long x2 = pack2(xbase[d * PROJ_TN + m]);
            #pragma unroll
            for (int j = 0; j < 4; j++) ffma2(acc[m][j], x2, w2[j]);
        }
    }

    #pragma unroll
    for (int m = 0; m < 6; m++) {
        int n = n0 + tr * 6 + m;
        if (n >= N_NODES) continue;
        float* orow = g_proj + ((size_t)r * N_NODES + n) * DIM + cg * 2;
        #pragma unroll
        for (int j = 0; j < 4; j++)
            *(unsigned long long*)(orow + 16 * j) = acc[m][j];
    }
}

// ---------------- att + aggregation, one 4-relation chunk ------------------
// Processes sorted slots in [off16[4c], off16[4c+4]) — a CONTIGUOUS range,
// so inactive blocks exit immediately and active blocks are fully dense
// (unlike R11's scattered predication). R9-proven 2-edges/half-warp body.
__global__ void __launch_bounds__(256) att_chunk_kernel(const float* __restrict__ efeat,
                                                        const float* __restrict__ nfeat,
                                                        float* __restrict__ hnb,
                                                        int c) {
    int lo = g_off16[c * 4], hi = g_off16[c * 4 + 4];
    int gt = blockIdx.x * blockDim.x + threadIdx.x;
    int p  = gt >> 4;
    int sl = threadIdx.x & 15;
    if (p >= N_EDGES / 2) return;
    int s0 = 2 * p, s1 = 2 * p + 1;
    bool act0 = (s0 >= lo) && (s0 < hi);
    bool act1 = (s1 >= lo) && (s1 < hi);
    if (!act0 && !act1) return;

    int4 ed0, ed1;
    float4 tv0, hv0, ev0, tv1, hv1, ev1;
    if (act0) {
        ed0 = g_sed[s0];
        tv0 = ((const float4*)(g_proj + ((size_t)ed0.w * N_NODES + ed0.x) * DIM))[sl];
        hv0 = ((const float4*)(g_proj + ((size_t)ed0.w * N_NODES + ed0.y) * DIM))[sl];
        ev0 = __ldcs(((const float4*)(efeat + (size_t)ed0.z * DIM)) + sl);
    }
    if (act1) {
        ed1 = g_sed[s1];
        tv1 = ((const float4*)(g_proj + ((size_t)ed1.w * N_NODES + ed1.x) * DIM))[sl];
        hv1 = ((const float4*)(g_proj + ((size_t)ed1.w * N_NODES + ed1.y) * DIM))[sl];
        ev1 = __ldcs(((const float4*)(efeat + (size_t)ed1.z * DIM)) + sl);
    }

    float val0 = 0.f, val1 = 0.f;
    if (act0)
        val0 = tv0.x * fast_tanh(hv0.x + ev0.x)
             + tv0.y * fast_tanh(hv0.y + ev0.y)
             + tv0.z * fast_tanh(hv0.z + ev0.z)
             + tv0.w * fast_tanh(hv0.w + ev0.w);
    if (act1)
        val1 = tv1.x * fast_tanh(hv1.x + ev1.x)
             + tv1.y * fast_tanh(hv1.y + ev1.y)
             + tv1.z * fast_tanh(hv1.z + ev1.z)
             + tv1.w * fast_tanh(hv1.w + ev1.w);

    #pragma unroll
    for (int off = 8; off; off >>= 1) {
        val0 += __shfl_xor_sync(0xffffffffu, val0, off);
        val1 += __shfl_xor_sync(0xffffffffu, val1, off);
    }

    if (act0) {
        float ex0 = __expf(val0);
        if (sl == 0) atomicAdd(&g_denom[ed0.y], ex0);
        float4 v0 = ((const float4*)(nfeat + (size_t)ed0.x * DIM))[sl];
        atomicAdd(((float4*)(hnb + (size_t)ed0.y * DIM)) + sl,
                  make_float4(ex0 * v0.x, ex0 * v0.y, ex0 * v0.z, ex0 * v0.w));
    }
    if (act1) {
        float ex1 = __expf(val1);
        if (sl == 0) atomicAdd(&g_denom[ed1.y], ex1);
        float4 v1 = ((const float4*)(nfeat + (size_t)ed1.x * DIM))[sl];
        atomicAdd(((float4*)(hnb + (size_t)ed1.y * DIM)) + sl,
                  make_float4(ex1 * v1.x, ex1 * v1.y, ex1 * v1.z, ex1 * v1.w));
    }
}

// ---------------- epilogue v2 (EXACT R12 config — proven ~25us) ------------
#define EPI_TN 128
__global__ void __launch_bounds__(256, 2) epilogue_kernel(const float* __restrict__ nfeat,
                                                          float* __restrict__ hnb,
                                                          const float* __restrict__ W1,
                                                          const float* __restrict__ W2,
                                                          float* __restrict__ out) {
    __shared__ __align__(16) float W1s[64 * 64];     // 16 KB
    __shared__ __align__(16) float W2s[64 * 64];     // 16 KB
    __shared__ __align__(16) float S0[64 * EPI_TN];  // 32 KB transposed [d][node]
    __shared__ __align__(16) float S1[64 * EPI_TN];  // 32 KB

    const int n0  = blockIdx.x * EPI_TN;
    const int tid = threadIdx.x;

    {
        const float4* w1src = (const float4*)W1;
        const float4* w2src = (const float4*)W2;
        float4* w1dst = (float4*)W1s;
        float4* w2dst = (float4*)W2s;
        #pragma unroll
        for (int i = tid; i < 1024; i += 256) { w1dst[i] = w1src[i]; w2dst[i] = w2src[i]; }
    }
    {
        int nn   = tid & 127;
        int half = tid >> 7;
        int n    = n0 + nn;
        if (n < N_NODES) {
            float den = g_denom[n];
            float inv = (den > 0.f) ? (1.f / den) : 0.f;
            const float4* a4 = (const float4*)(nfeat + (size_t)n * DIM);
            float4*       b4 = (float4*)(hnb + (size_t)n * DIM);
            #pragma unroll
            for (int c4 = half * 8; c4 < half * 8 + 8; c4++) {
                float4 a = a4[c4];
                float4 b = b4[c4];
                b = make_float4(b.x * inv, b.y * inv, b.z * inv, b.w * inv);
                b4[c4] = b;                      // normalized hnb = output #1
                S0[(c4 * 4 + 0) * EPI_TN + nn] = a.x + b.x;
                S0[(c4 * 4 + 1) * EPI_TN + nn] = a.y + b.y;
                S0[(c4 * 4 + 2) * EPI_TN + nn] = a.z + b.z;
                S0[(c4 * 4 + 3) * EPI_TN + nn] = a.w + b.w;
                S1[(c4 * 4 + 0) * EPI_TN + nn] = a.x * b.x;
                S1[(c4 * 4 + 1) * EPI_TN + nn] = a.y * b.y;
                S1[(c4 * 4 + 2) * EPI_TN + nn] = a.z * b.z;
                S1[(c4 * 4 + 3) * EPI_TN + nn] = a.w * b.w;
            }
        } else {
            #pragma unroll
            for (int c4 = half * 8; c4 < half * 8 + 8; c4++) {
                #pragma unroll
                for (int q = 0; q < 4; q++) {
                    S0[(c4 * 4 + q) * EPI_TN + nn] = 0.f;
                    S1[(c4 * 4 + q) * EPI_TN + nn] = 0.f;
                }
            }
        }
    }
    __syncthreads();

    const int cg = tid & 7;
    const int tr = tid >> 3;
    const float* w1base = W1s + cg * 2;
    const float* w2base = W2s + cg * 2;
    const float* xb0 = S0 + tr * 4;
    const float* xb1 = S1 + tr * 4;

    unsigned long long acc1[4][4], acc2[4][4];
    #pragma unroll
    for (int m = 0; m < 4; m++)
        #pragma unroll
        for (int j = 0; j < 4; j++) { acc1[m][j] = 0ull; acc2[m][j] = 0ull; }

    #pragma unroll 4
    for (int d = 0; d < 64; d++) {
        unsigned long long w1v[4], w2v[4];
        #pragma unroll
        for (int j = 0; j < 4; j++) {
            w1v[j] = *(const unsigned long long*)(w1base + d * 64 + 16 * j);
            w2v[j] = *(const unsigned long long*)(w2base + d * 64 + 16 * j);
        }
        #pragma unroll
        for (int m = 0; m < 4; m++) {
            unsigned long long x0 = pack2(xb0[d * EPI_TN + m]);
            unsigned long long x1 = pack2(xb1[d * EPI_TN + m]);
            #pragma unroll
            for (int j = 0; j < 4; j++) {
                ffma2(acc1[m][j], x0, w1v[j]);
                ffma2(acc2[m][j], x1, w2v[j]);
            }
        }
    }

    #pragma unroll
    for (int m = 0; m < 4; m++) {
        int n = n0 + tr * 4 + m;
        if (n >= N_NODES) continue;
        float* orow = out + (size_t)n * DIM + cg * 2;
        #pragma unroll
        for (int j = 0; j < 4; j++) {
            float lo1, hi1, lo2, hi2;
            unpack2(acc1[m][j], lo1, hi1);
            unpack2(acc2[m][j], lo2, hi2);
            orow[16 * j]     = leaky(lo1) + leaky(lo2);
            orow[16 * j + 1] = leaky(hi1) + leaky(hi2);
        }
    }
}

// ---------------- launch: fork/join two streams inside capture -------------
extern "C" void kernel_launch(void* const* d_in, const int* in_sizes, int n_in,
                              void* d_out, int out_size) {
    const float* nfeat = (const float*)d_in[0];
    const float* efeat = (const float*)d_in[1];
    const float* relW  = (const float*)d_in[2];
    const float* W1    = (const float*)d_in[3];
    const float* W2    = (const float*)d_in[4];
    const int*   src   = (const int*)d_in[5];
    const int*   dst   = (const int*)d_in[6];
    const int*   etype = (const int*)d_in[7];

    float* hnb  = (float*)d_out;
    float* out2 = (float*)d_out + (size_t)N_NODES * DIM;

    // second stream + events (created per call; leaked — kernel_launch is
    // invoked only a handful of times, never during timed replays)
    cudaStream_t sB;
    cudaStreamCreateWithFlags(&sB, cudaStreamNonBlocking);
    cudaEvent_t evFork, evP[4], evJoin;
    cudaEventCreateWithFlags(&evFork, cudaEventDisableTiming);
    cudaEventCreateWithFlags(&evJoin, cudaEventDisableTiming);
    for (int i = 0; i < 4; i++) cudaEventCreateWithFlags(&evP[i], cudaEventDisableTiming);

    const int AB = (N_EDGES / 2 * 16 + 255) / 256;   // 25000

    // stream A (default): init
    init_kernel<<<(N_NODES * DIM / 4 + 255) / 256, 256>>>(hnb);
    cudaEventRecord(evFork, 0);

    // stream B: sort by etype (only needs inputs; overlaps proj chunk 0)
    cudaStreamWaitEvent(sB, evFork, 0);
    hist16_kernel<<<512, 256, 0, sB>>>(etype);
    scan16_kernel<<<1, 32, 0, sB>>>();
    scatter16_kernel<<<(N_EDGES + 255) / 256, 256, 0, sB>>>(src, dst, etype);

    // stream A: proj in 4 chunks of 4 relations, event after each
    dim3 gp((N_NODES + PROJ_TN - 1) / PROJ_TN, 4);
    for (int c = 0; c < 4; c++) {
        proj_kernel<<<gp, 256>>>(nfeat, relW, c * 4);
        cudaEventRecord(evP[c], 0);
    }

    // stream B: att chunk c after proj chunk c
    for (int c = 0; c < 4; c++) {
        cudaStreamWaitEvent(sB, evP[c], 0);
        att_chunk_kernel<<<AB, 256, 0, sB>>>(efeat, nfeat, hnb, c);
    }
    cudaEventRecord(evJoin, sB);

    // stream A: epilogue after all att chunks
    cudaStreamWaitEvent(0, evJoin, 0);
    epilogue_kernel<<<(N_NODES + EPI_TN - 1) / EPI_TN, 256>>>(nfeat, hnb, W1, W2, out2);
}

// round 14
// speedup vs baseline: 1.1780x; 1.1780x over previous
#include <cuda_runtime.h>
#include <cstdint>

#define N_NODES 50000
#define N_EDGES 800000
#define DIM     64
#define N_REL   16

// ---------------- scratch (device globals: allocation-free) ----------------
__device__ float g_proj[(size_t)N_REL * N_NODES * DIM];  // 204.8 MB
__device__ float g_denom[N_NODES];

// ---------------- helpers ----------------
__device__ __forceinline__ float fast_tanh(float x) {
    float xc = fminf(fmaxf(x, -15.f), 15.f);
    float t  = __expf(2.f * xc);
    return __fdividef(t - 1.f, t + 1.f);
}
__device__ __forceinline__ unsigned long long pack2(float x) {
    unsigned long long r;
    asm("mov.b64 %0, {%1, %1};" : "=l"(r) : "f"(x));
    return r;
}
__device__ __forceinline__ void ffma2(unsigned long long& d,
                                      unsigned long long a,
                                      unsigned long long b) {
    asm("fma.rn.f32x2 %0, %1, %2, %0;" : "+l"(d) : "l"(a), "l"(b));
}
__device__ __forceinline__ void unpack2(unsigned long long v, float& lo, float& hi) {
    asm("mov.b64 {%0, %1}, %2;" : "=f"(lo), "=f"(hi) : "l"(v));
}
__device__ __forceinline__ float leaky(float x) { return x >= 0.f ? x : 0.01f * x; }
__device__ __forceinline__ float4 ldcg4(const float4* p) {   // L1-bypass gather
    float4 v;
    asm volatile("ld.global.cg.v4.f32 {%0,%1,%2,%3}, [%4];"
                 : "=f"(v.x), "=f"(v.y), "=f"(v.z), "=f"(v.w) : "l"(p));
    return v;
}

// ---------------- launch #1: zero hnb accumulator + denom ----------------
__global__ void init_kernel(float* __restrict__ hnb) {
    int i = blockIdx.x * blockDim.x + threadIdx.x;
    if (i < N_NODES * DIM / 4) ((float4*)hnb)[i] = make_float4(0.f, 0.f, 0.f, 0.f);
    if (i < N_NODES) g_denom[i] = 0.f;
}

// ---------------- launch #2: proj, ALL 16 relations (EXACT R8 inner config)
#define PROJ_TN 192
__global__ void __launch_bounds__(256, 3) proj_kernel(const float* __restrict__ nfeat,
                                                      const float* __restrict__ relW) {
    __shared__ __align__(16) float Ws[64 * 64];          // 16 KB [d][col]
    __shared__ __align__(16) float Xs[64 * PROJ_TN];     // 48 KB transposed [d][node]

    const int r   = blockIdx.y;
    const int n0  = blockIdx.x * PROJ_TN;
    const int tid = threadIdx.x;

    {
        const float4* wsrc = (const float4*)(relW + (size_t)r * 4096);
        float4* wdst = (float4*)Ws;
        #pragma unroll
        for (int i = tid; i < 1024; i += 256) wdst[i] = wsrc[i];
    }
    if (tid < PROJ_TN) {
        int n = n0 + tid;
        if (n < N_NODES) {
            const float4* nr = (const float4*)(nfeat + (size_t)n * DIM);
            #pragma unroll
            for (int c4 = 0; c4 < 16; c4++) {
                float4 v = nr[c4];
                Xs[(c4 * 4 + 0) * PROJ_TN + tid] = v.x;
                Xs[(c4 * 4 + 1) * PROJ_TN + tid] = v.y;
                Xs[(c4 * 4 + 2) * PROJ_TN + tid] = v.z;
                Xs[(c4 * 4 + 3) * PROJ_TN + tid] = v.w;
            }
        } else {
            #pragma unroll
            for (int c = 0; c < 64; c++) Xs[c * PROJ_TN + tid] = 0.f;
        }
    }
    __syncthreads();

    const int cg = tid & 7;
    const int tr = tid >> 3;
    const float* wbase = Ws + cg * 2;      // + d*64 + 16*j
    const float* xbase = Xs + tr * 6;      // + d*PROJ_TN + m

    unsigned long long acc[6][4];
    #pragma unroll
    for (int m = 0; m < 6; m++)
        #pragma unroll
        for (int j = 0; j < 4; j++) acc[m][j] = 0ull;

    #pragma unroll 4
    for (int d = 0; d < 64; d++) {
        unsigned long long w2[4];
        #pragma unroll
        for (int j = 0; j < 4; j++)
            w2[j] = *(const unsigned long long*)(wbase + d * 64 + 16 * j);
        #pragma unroll
        for (int m = 0; m < 6; m++) {
            unsigned long long x2 = pack2(xbase[d * PROJ_TN + m]);
            #pragma unroll
            for (int j = 0; j < 4; j++) ffma2(acc[m][j], x2, w2[j]);
        }
    }

    #pragma unroll
    for (int m = 0; m < 6; m++) {
        int n = n0 + tr * 6 + m;
        if (n >= N_NODES) continue;
        float* orow = g_proj + ((size_t)r * N_NODES + n) * DIM + cg * 2;
        #pragma unroll
        for (int j = 0; j < 4; j++)
            *(unsigned long long*)(orow + 16 * j) = acc[m][j];
    }
}

// ---------------- launch #3: att + aggregation (R9 config + L1-bypass) -----
__global__ void __launch_bounds__(256) att_fused_kernel(const float* __restrict__ efeat,
                                                        const float* __restrict__ nfeat,
                                                        const int* __restrict__ src,
                                                        const int* __restrict__ dst,
                                                        const int* __restrict__ etype,
                                                        float* __restrict__ hnb) {
    int gt = blockIdx.x * blockDim.x + threadIdx.x;
    int p  = gt >> 4;                 // pair of edges
    int sl = threadIdx.x & 15;
    if (p >= N_EDGES / 2) return;     // N_EDGES even

    int2 s2 = ((const int2*)src)[p];
    int2 d2 = ((const int2*)dst)[p];
    int2 r2 = ((const int2*)etype)[p];
    int e0 = 2 * p, e1 = 2 * p + 1;

    // proj gathers: .cg (skip L1 — 205MB footprint never re-hits L1; keep L1
    // for nfeat rows which are genuinely hot). efeat: .cs streaming.
    float4 tv0 = ldcg4(((const float4*)(g_proj + ((size_t)r2.x * N_NODES + s2.x) * DIM)) + sl);
    float4 hv0 = ldcg4(((const float4*)(g_proj + ((size_t)r2.x * N_NODES + d2.x) * DIM)) + sl);
    float4 tv1 = ldcg4(((const float4*)(g_proj + ((size_t)r2.y * N_NODES + s2.y) * DIM)) + sl);
    float4 hv1 = ldcg4(((const float4*)(g_proj + ((size_t)r2.y * N_NODES + d2.y) * DIM)) + sl);
    float4 ev0 = __ldcs(((const float4*)(efeat + (size_t)e0 * DIM)) + sl);
    float4 ev1 = __ldcs(((const float4*)(efeat + (size_t)e1 * DIM)) + sl);

    float val0 = tv0.x * fast_tanh(hv0.x + ev0.x)
               + tv0.y * fast_tanh(hv0.y + ev0.y)
               + tv0.z * fast_tanh(hv0.z + ev0.z)
               + tv0.w * fast_tanh(hv0.w + ev0.w);
    float val1 = tv1.x * fast_tanh(hv1.x + ev1.x)
               + tv1.y * fast_tanh(hv1.y + ev1.y)
               + tv1.z * fast_tanh(hv1.z + ev1.z)
               + tv1.w * fast_tanh(hv1.w + ev1.w);

    #pragma unroll
    for (int off = 8; off; off >>= 1) {
        val0 += __shfl_xor_sync(0xffffffffu, val0, off);
        val1 += __shfl_xor_sync(0xffffffffu, val1, off);
    }

    float ex0 = __expf(val0);
    float ex1 = __expf(val1);

    if (sl == 0) {
        atomicAdd(&g_denom[d2.x], ex0);
        atomicAdd(&g_denom[d2.y], ex1);
    }
    {
        float4 v0 = ((const float4*)(nfeat + (size_t)s2.x * DIM))[sl];
        float4 v1 = ((const float4*)(nfeat + (size_t)s2.y * DIM))[sl];
        atomicAdd(((float4*)(hnb + (size_t)d2.x * DIM)) + sl,
                  make_float4(ex0 * v0.x, ex0 * v0.y, ex0 * v0.z, ex0 * v0.w));
        atomicAdd(((float4*)(hnb + (size_t)d2.y * DIM)) + sl,
                  make_float4(ex1 * v1.x, ex1 * v1.y, ex1 * v1.z, ex1 * v1.w));
    }
}

// ---------------- launch #4: epilogue v2 (EXACT R12 config) <- ncu slot ----
#define EPI_TN 128
__global__ void __launch_bounds__(256, 2) epilogue_kernel(const float* __restrict__ nfeat,
                                                          float* __restrict__ hnb,
                                                          const float* __restrict__ W1,
                                                          const float* __restrict__ W2,
                                                          float* __restrict__ out) {
    __shared__ __align__(16) float W1s[64 * 64];     // 16 KB
    __shared__ __align__(16) float W2s[64 * 64];     // 16 KB
    __shared__ __align__(16) float S0[64 * EPI_TN];  // 32 KB transposed [d][node]
    __shared__ __align__(16) float S1[64 * EPI_TN];  // 32 KB

    const int n0  = blockIdx.x * EPI_TN;
    const int tid = threadIdx.x;

    {
        const float4* w1src = (const float4*)W1;
        const float4* w2src = (const float4*)W2;
        float4* w1dst = (float4*)W1s;
        float4* w2dst = (float4*)W2s;
        #pragma unroll
        for (int i = tid; i < 1024; i += 256) { w1dst[i] = w1src[i]; w2dst[i] = w2src[i]; }
    }
    {
        int nn   = tid & 127;
        int half = tid >> 7;
        int n    = n0 + nn;
        if (n < N_NODES) {
            float den = g_denom[n];
            float inv = (den > 0.f) ? (1.f / den) : 0.f;
            const float4* a4 = (const float4*)(nfeat + (size_t)n * DIM);
            float4*       b4 = (float4*)(hnb + (size_t)n * DIM);
            #pragma unroll
            for (int c4 = half * 8; c4 < half * 8 + 8; c4++) {
                float4 a = a4[c4];
                float4 b = b4[c4];
                b = make_float4(b.x * inv, b.y * inv, b.z * inv, b.w * inv);
                b4[c4] = b;                      // normalized hnb = output #1
                S0[(c4 * 4 + 0) * EPI_TN + nn] = a.x + b.x;
                S0[(c4 * 4 + 1) * EPI_TN + nn] = a.y + b.y;
                S0[(c4 * 4 + 2) * EPI_TN + nn] = a.z + b.z;
                S0[(c4 * 4 + 3) * EPI_TN + nn] = a.w + b.w;
                S1[(c4 * 4 + 0) * EPI_TN + nn] = a.x * b.x;
                S1[(c4 * 4 + 1) * EPI_TN + nn] = a.y * b.y;
                S1[(c4 * 4 + 2) * EPI_TN + nn] = a.z * b.z;
                S1[(c4 * 4 + 3) * EPI_TN + nn] = a.w * b.w;
            }
        } else {
            #pragma unroll
            for (int c4 = half * 8; c4 < half * 8 + 8; c4++) {
                #pragma unroll
                for (int q = 0; q < 4; q++) {
                    S0[(c4 * 4 + q) * EPI_TN + nn] = 0.f;
                    S1[(c4 * 4 + q) * EPI_TN + nn] = 0.f;
                }
            }
        }
    }
    __syncthreads();

    const int cg = tid & 7;
    const int tr = tid >> 3;
    const float* w1base = W1s + cg * 2;
    const float* w2base = W2s + cg * 2;
    const float* xb0 = S0 + tr * 4;
    const float* xb1 = S1 + tr * 4;

    unsigned long long acc1[4][4], acc2[4][4];
    #pragma unroll
    for (int m = 0; m < 4; m++)
        #pragma unroll
        for (int j = 0; j < 4; j++) { acc1[m][j] = 0ull; acc2[m][j] = 0ull; }

    #pragma unroll 4
    for (int d = 0; d < 64; d++) {
        unsigned long long w1v[4], w2v[4];
        #pragma unroll
        for (int j = 0; j < 4; j++) {
            w1v[j] = *(const unsigned long long*)(w1base + d * 64 + 16 * j);
            w2v[j] = *(const unsigned long long*)(w2base + d * 64 + 16 * j);
        }
        #pragma unroll
        for (int m = 0; m < 4; m++) {
            unsigned long long x0 = pack2(xb0[d * EPI_TN + m]);
            unsigned long long x1 = pack2(xb1[d * EPI_TN + m]);
            #pragma unroll
            for (int j = 0; j < 4; j++) {
                ffma2(acc1[m][j], x0, w1v[j]);
                ffma2(acc2[m][j], x1, w2v[j]);
            }
        }
    }

    #pragma unroll
    for (int m = 0; m < 4; m++) {
        int n = n0 + tr * 4 + m;
        if (n >= N_NODES) continue;
        float* orow = out + (size_t)n * DIM + cg * 2;
        #pragma unroll
        for (int j = 0; j < 4; j++) {
            float lo1, hi1, lo2, hi2;
            unpack2(acc1[m][j], lo1, hi1);
            unpack2(acc2[m][j], lo2, hi2);
            orow[16 * j]     = leaky(lo1) + leaky(lo2);
            orow[16 * j + 1] = leaky(hi1) + leaky(hi2);
        }
    }
}

// ---------------- launch ----------------
extern "C" void kernel_launch(void* const* d_in, const int* in_sizes, int n_in,
                              void* d_out, int out_size) {
    const float* nfeat = (const float*)d_in[0];
    const float* efeat = (const float*)d_in[1];
    const float* relW  = (const float*)d_in[2];
    const float* W1    = (const float*)d_in[3];
    const float* W2    = (const float*)d_in[4];
    const int*   src   = (const int*)d_in[5];
    const int*   dst   = (const int*)d_in[6];
    const int*   etype = (const int*)d_in[7];

    float* hnb  = (float*)d_out;
    float* out2 = (float*)d_out + (size_t)N_NODES * DIM;

    // #1
    init_kernel<<<(N_NODES * DIM / 4 + 255) / 256, 256>>>(hnb);
    // #2  (single launch: all 16 relations, one tail wave)
    dim3 g1((N_NODES + PROJ_TN - 1) / PROJ_TN, N_REL);
    proj_kernel<<<g1, 256>>>(nfeat, relW);
    // #3
    att_fused_kernel<<<(N_EDGES / 2 * 16 + 255) / 256, 256>>>(efeat, nfeat, src, dst, etype, hnb);
    // #4  <- ncu profiles this launch (epilogue v2, first measurement)
    epilogue_kernel<<<(N_NODES + EPI_TN - 1) / EPI_TN, 256>>>(nfeat, hnb, W1, W2, out2);
}

// round 16
// speedup vs baseline: 1.4792x; 1.2556x over previous
#include <cuda_runtime.h>
#include <cuda_bf16.h>
#include <cstdint>

#define N_NODES 50000
#define N_EDGES 800000
#define DIM     64
#define N_REL   16

// ---------------- scratch (device globals: allocation-free) ----------------
__device__ float g_proj[(size_t)N_REL * N_NODES * DIM];  // 204.8 MB
__device__ float g_denom[N_NODES];

// ---------------- generic helpers ----------------
__device__ __forceinline__ float fast_tanh(float x) {
    float xc = fminf(fmaxf(x, -15.f), 15.f);
    float t  = __expf(2.f * xc);
    return __fdividef(t - 1.f, t + 1.f);
}
__device__ __forceinline__ unsigned long long pack2(float x) {
    unsigned long long r;
    asm("mov.b64 %0, {%1, %1};" : "=l"(r) : "f"(x));
    return r;
}
__device__ __forceinline__ void ffma2(unsigned long long& d,
                                      unsigned long long a,
                                      unsigned long long b) {
    asm("fma.rn.f32x2 %0, %1, %2, %0;" : "+l"(d) : "l"(a), "l"(b));
}
__device__ __forceinline__ void unpack2(unsigned long long v, float& lo, float& hi) {
    asm("mov.b64 {%0, %1}, %2;" : "=f"(lo), "=f"(hi) : "l"(v));
}
__device__ __forceinline__ float leaky(float x) { return x >= 0.f ? x : 0.01f * x; }
__device__ __forceinline__ float4 ldcg4(const float4* p) {
    float4 v;
    asm volatile("ld.global.cg.v4.f32 {%0,%1,%2,%3}, [%4];"
                 : "=f"(v.x), "=f"(v.y), "=f"(v.z), "=f"(v.w) : "l"(p));
    return v;
}
__device__ __forceinline__ uint32_t smem_to_u32(const void* p) {
    uint32_t a;
    asm("{ .reg .u64 t; cvta.to.shared.u64 t, %1; cvt.u32.u64 %0, t; }"
        : "=r"(a) : "l"(p));
    return a;
}
__device__ __forceinline__ uint32_t bfpack(float a, float b) {
    __nv_bfloat16 ha = __float2bfloat16(a), hb = __float2bfloat16(b);
    return (uint32_t)__bfloat16_as_ushort(hb) << 16 | __bfloat16_as_ushort(ha);
}

// ---------------- mma.sync / ldmatrix wrappers (sm_80+ path) ----------------
__device__ __forceinline__ void mma_bf16(float c[4],
                                         uint32_t a0, uint32_t a1, uint32_t a2, uint32_t a3,
                                         uint32_t b0, uint32_t b1) {
    asm volatile("mma.sync.aligned.m16n8k16.row.col.f32.bf16.bf16.f32 "
                 "{%0,%1,%2,%3}, {%4,%5,%6,%7}, {%8,%9}, {%0,%1,%2,%3};"
                 : "+f"(c[0]), "+f"(c[1]), "+f"(c[2]), "+f"(c[3])
                 : "r"(a0), "r"(a1), "r"(a2), "r"(a3), "r"(b0), "r"(b1));
}
__device__ __forceinline__ void ldsm_x4(uint32_t& r0, uint32_t& r1, uint32_t& r2, uint32_t& r3,
                                        uint32_t addr) {
    asm volatile("ldmatrix.sync.aligned.m8n8.x4.shared.b16 {%0,%1,%2,%3}, [%4];"
                 : "=r"(r0), "=r"(r1), "=r"(r2), "=r"(r3) : "r"(addr));
}
__device__ __forceinline__ void ldsm_x4_t(uint32_t& r0, uint32_t& r1, uint32_t& r2, uint32_t& r3,
                                          uint32_t addr) {
    asm volatile("ldmatrix.sync.aligned.m8n8.x4.trans.shared.b16 {%0,%1,%2,%3}, [%4];"
                 : "=r"(r0), "=r"(r1), "=r"(r2), "=r"(r3) : "r"(addr));
}

// ---------------- launch #1: zero hnb ----------------
__global__ void init_hnb_kernel(float* __restrict__ hnb) {
    int i = blockIdx.x * blockDim.x + threadIdx.x;
    if (i < N_NODES * DIM / 4) ((float4*)hnb)[i] = make_float4(0.f, 0.f, 0.f, 0.f);
}
// ---------------- launch #2: zero denom ----------------
__global__ void init_denom_kernel() {
    int i = blockIdx.x * blockDim.x + threadIdx.x;
    if (i < N_NODES) g_denom[i] = 0.f;
}

// ---------------- launches #3/#4: bf16x3 proj via mma.sync -----------------
// CTA = 128-node tile x 4 relations. X -> hi/lo bf16 smem once (ld=72 pad:
// 144B row stride spreads 8 ldmatrix rows over all banks). Per relation:
// W -> hi/lo smem; per warp (rows w*16..+15): 4 k-chunks x
// [A-ldmatrix hi/lo + B-ldmatrix.trans hi/lo + 24 HMMA (3 bf16x3 splits x
// 8 n-tiles)] accumulating f32; direct float2 stores to g_proj.
#define X_LD 72
#define W_LD 72
#define SM_XHI 0
#define SM_XLO 18432
#define SM_WHI 36864
#define SM_WLO 46080
#define SM_TOTAL 55296

__global__ void __launch_bounds__(256) proj_mma_kernel(const float* __restrict__ nfeat,
                                                       const float* __restrict__ relW,
                                                       int g_base) {
    extern __shared__ unsigned char sm[];
    uint16_t* Xhi = (uint16_t*)(sm + SM_XHI);
    uint16_t* Xlo = (uint16_t*)(sm + SM_XLO);
    uint16_t* Whi = (uint16_t*)(sm + SM_WHI);
    uint16_t* Wlo = (uint16_t*)(sm + SM_WLO);

    const int tid  = threadIdx.x;
    const int lane = tid & 31;
    const int w    = tid >> 5;                 // 0..7
    const int n0   = blockIdx.x * 128;
    const int rbase = (g_base + blockIdx.y) * 4;

    // ---- X tile -> bf16 hi/lo smem (each thread: half a row = 32 cols) ----
    {
        int row  = tid >> 1, half = tid & 1;
        int n    = n0 + row;
        bool valid = (n < N_NODES);
        const float4* nr = (const float4*)(nfeat + (size_t)n * DIM) + half * 8;
        uint32_t* xh = (uint32_t*)&Xhi[row * X_LD + half * 32];
        uint32_t* xl = (uint32_t*)&Xlo[row * X_LD + half * 32];
        #pragma unroll
        for (int q = 0; q < 8; q++) {
            float4 v = valid ? nr[q] : make_float4(0.f, 0.f, 0.f, 0.f);
            __nv_bfloat16 h0 = __float2bfloat16(v.x), h1 = __float2bfloat16(v.y);
            __nv_bfloat16 h2 = __float2bfloat16(v.z), h3 = __float2bfloat16(v.w);
            xh[q * 2]     = (uint32_t)__bfloat16_as_ushort(h1) << 16 | __bfloat16_as_ushort(h0);
            xh[q * 2 + 1] = (uint32_t)__bfloat16_as_ushort(h3) << 16 | __bfloat16_as_ushort(h2);
            xl[q * 2]     = bfpack(v.x - __bfloat162float(h0), v.y - __bfloat162float(h1));
            xl[q * 2 + 1] = bfpack(v.z - __bfloat162float(h2), v.w - __bfloat162float(h3));
        }
    }

    // ldmatrix base addresses (lane-dependent, loop-invariant)
    uint32_t aHi = smem_to_u32(&Xhi[(w * 16 + (lane & 15)) * X_LD]) + (lane >> 4) * 16;
    uint32_t aLo = smem_to_u32(&Xlo[(w * 16 + (lane & 15)) * X_LD]) + (lane >> 4) * 16;
    int bk = (lane & 7) + ((lane >> 3) & 1) * 8;   // k row within chunk
    int bn = (lane >> 4) * 8;                      // n sub-block
    uint32_t bHi = smem_to_u32(&Whi[bk * W_LD + bn]);
    uint32_t bLo = smem_to_u32(&Wlo[bk * W_LD + bn]);

    #pragma unroll 1
    for (int ri = 0; ri < 4; ri++) {
        const int r = rbase + ri;
        __syncthreads();   // prior ldmatrix reads done before W overwrite
        // ---- W_r -> bf16 hi/lo smem (thread: row=tid>>2, 16 cols) ----
        {
            int row = tid >> 2, q4 = tid & 3;
            const float4* wr = (const float4*)(relW + (size_t)r * 4096 + row * 64 + q4 * 16);
            uint32_t* wh = (uint32_t*)&Whi[row * W_LD + q4 * 16];
            uint32_t* wl = (uint32_t*)&Wlo[row * W_LD + q4 * 16];
            #pragma unroll
            for (int q = 0; q < 4; q++) {
                float4 v = wr[q];
                __nv_bfloat16 h0 = __float2bfloat16(v.x), h1 = __float2bfloat16(v.y);
                __nv_bfloat16 h2 = __float2bfloat16(v.z), h3 = __float2bfloat16(v.w);
                wh[q * 2]     = (uint32_t)__bfloat16_as_ushort(h1) << 16 | __bfloat16_as_ushort(h0);
                wh[q * 2 + 1] = (uint32_t)__bfloat16_as_ushort(h3) << 16 | __bfloat16_as_ushort(h2);
                wl[q * 2]     = bfpack(v.x - __bfloat162float(h0), v.y - __bfloat162float(h1));
                wl[q * 2 + 1] = bfpack(v.z - __bfloat162float(h2), v.w - __bfloat162float(h3));
            }
        }
        __syncthreads();

        float acc[8][4];
        #pragma unroll
        for (int nt = 0; nt < 8; nt++)
            #pragma unroll
            for (int q = 0; q < 4; q++) acc[nt][q] = 0.f;

        #pragma unroll
        for (int kc = 0; kc < 4; kc++) {
            uint32_t ah[4], al[4];
            ldsm_x4(ah[0], ah[1], ah[2], ah[3], aHi + kc * 32);
            ldsm_x4(al[0], al[1], al[2], al[3], aLo + kc * 32);

            uint32_t bh[16];
            #pragma unroll
            for (int pi = 0; pi < 4; pi++)
                ldsm_x4_t(bh[pi * 4], bh[pi * 4 + 1], bh[pi * 4 + 2], bh[pi * 4 + 3],
                          bHi + kc * 16 * W_LD * 2 + pi * 32);
            #pragma unroll
            for (int nt = 0; nt < 8; nt++) {
                int bi = (nt >> 1) * 4 + (nt & 1) * 2;
                mma_bf16(acc[nt], ah[0], ah[1], ah[2], ah[3], bh[bi], bh[bi + 1]);
            }
            #pragma unroll
            for (int nt = 0; nt < 8; nt++) {
                int bi = (nt >> 1) * 4 + (nt & 1) * 2;
                mma_bf16(acc[nt], al[0], al[1], al[2], al[3], bh[bi], bh[bi + 1]);
            }
            uint32_t bl[16];
            #pragma unroll
            for (int pi = 0; pi < 4; pi++)
                ldsm_x4_t(bl[pi * 4], bl[pi * 4 + 1], bl[pi * 4 + 2], bl[pi * 4 + 3],
                          bLo + kc * 16 * W_LD * 2 + pi * 32);
            #pragma unroll
            for (int nt = 0; nt < 8; nt++) {
                int bi = (nt >> 1) * 4 + (nt & 1) * 2;
                mma_bf16(acc[nt], ah[0], ah[1], ah[2], ah[3], bl[bi], bl[bi + 1]);
            }
        }

        // ---- store: thread owns rows (w*16 + lane/4, +8), cols nt*8+(lane&3)*2
        int row0 = n0 + w * 16 + (lane >> 2);
        float* obase = g_proj + (size_t)r * N_NODES * DIM;
        #pragma unroll
        for (int nt = 0; nt < 8; nt++) {
            int col = nt * 8 + (lane & 3) * 2;
            if (row0 < N_NODES)
                *(float2*)(obase + (size_t)row0 * DIM + col) = make_float2(acc[nt][0], acc[nt][1]);
            if (row0 + 8 < N_NODES)
                *(float2*)(obase + (size_t)(row0 + 8) * DIM + col) = make_float2(acc[nt][2], acc[nt][3]);
        }
    }
}

// ---------------- launch #5: att + aggregation (EXACT R14 config) ----------
__global__ void __launch_bounds__(256) att_fused_kernel(const float* __restrict__ efeat,
                                                        const float* __restrict__ nfeat,
                                                        const int* __restrict__ src,
                                                        const int* __restrict__ dst,
                                                        const int* __restrict__ etype,
                                                        float* __restrict__ hnb) {
    int gt = blockIdx.x * blockDim.x + threadIdx.x;
    int p  = gt >> 4;
    int sl = threadIdx.x & 15;
    if (p >= N_EDGES / 2) return;

    int2 s2 = ((const int2*)src)[p];
    int2 d2 = ((const int2*)dst)[p];
    int2 r2 = ((const int2*)etype)[p];
    int e0 = 2 * p, e1 = 2 * p + 1;

    float4 tv0 = ldcg4(((const float4*)(g_proj + ((size_t)r2.x * N_NODES + s2.x) * DIM)) + sl);
    float4 hv0 = ldcg4(((const float4*)(g_proj + ((size_t)r2.x * N_NODES + d2.x) * DIM)) + sl);
    float4 tv1 = ldcg4(((const float4*)(g_proj + ((size_t)r2.y * N_NODES + s2.y) * DIM)) + sl);
    float4 hv1 = ldcg4(((const float4*)(g_proj + ((size_t)r2.y * N_NODES + d2.y) * DIM)) + sl);
    float4 ev0 = __ldcs(((const float4*)(efeat + (size_t)e0 * DIM)) + sl);
    float4 ev1 = __ldcs(((const float4*)(efeat + (size_t)e1 * DIM)) + sl);

    float val0 = tv0.x * fast_tanh(hv0.x + ev0.x)
               + tv0.y * fast_tanh(hv0.y + ev0.y)
               + tv0.z * fast_tanh(hv0.z + ev0.z)
               + tv0.w * fast_tanh(hv0.w + ev0.w);
    float val1 = tv1.x * fast_tanh(hv1.x + ev1.x)
               + tv1.y * fast_tanh(hv1.y + ev1.y)
               + tv1.z * fast_tanh(hv1.z + ev1.z)
               + tv1.w * fast_tanh(hv1.w + ev1.w);

    #pragma unroll
    for (int off = 8; off; off >>= 1) {
        val0 += __shfl_xor_sync(0xffffffffu, val0, off);
        val1 += __shfl_xor_sync(0xffffffffu, val1, off);
    }

    float ex0 = __expf(val0);
    float ex1 = __expf(val1);

    if (sl == 0) {
        atomicAdd(&g_denom[d2.x], ex0);
        atomicAdd(&g_denom[d2.y], ex1);
    }
    {
        float4 v0 = ((const float4*)(nfeat + (size_t)s2.x * DIM))[sl];
        float4 v1 = ((const float4*)(nfeat + (size_t)s2.y * DIM))[sl];
        atomicAdd(((float4*)(hnb + (size_t)d2.x * DIM)) + sl,
                  make_float4(ex0 * v0.x, ex0 * v0.y, ex0 * v0.z, ex0 * v0.w));
        atomicAdd(((float4*)(hnb + (size_t)d2.y * DIM)) + sl,
                  make_float4(ex1 * v1.x, ex1 * v1.y, ex1 * v1.z, ex1 * v1.w));
    }
}

// ---------------- launch #6: epilogue v2 (EXACT R12/R14 config) ------------
#define EPI_TN 128
__global__ void __launch_bounds__(256, 2) epilogue_kernel(const float* __restrict__ nfeat,
                                                          float* __restrict__ hnb,
                                                          const float* __restrict__ W1,
                                                          const float* __restrict__ W2,
                                                          float* __restrict__ out) {
    __shared__ __align__(16) float W1s[64 * 64];
    __shared__ __align__(16) float W2s[64 * 64];
    __shared__ __align__(16) float S0[64 * EPI_TN];
    __shared__ __align__(16) float S1[64 * EPI_TN];

    const int n0  = blockIdx.x * EPI_TN;
    const int tid = threadIdx.x;

    {
        const float4* w1src = (const float4*)W1;
        const float4* w2src = (const float4*)W2;
        float4* w1dst = (float4*)W1s;
        float4* w2dst = (float4*)W2s;
        #pragma unroll
        for (int i = tid; i < 1024; i += 256) { w1dst[i] = w1src[i]; w2dst[i] = w2src[i]; }
    }
    {
        int nn   = tid & 127;
        int half = tid >> 7;
        int n    = n0 + nn;
        if (n < N_NODES) {
            float den = g_denom[n];
            float inv = (den > 0.f) ? (1.f / den) : 0.f;
            const float4* a4 = (const float4*)(nfeat + (size_t)n * DIM);
            float4*       b4 = (float4*)(hnb + (size_t)n * DIM);
            #pragma unroll
            for (int c4 = half * 8; c4 < half * 8 + 8; c4++) {
                float4 a = a4[c4];
                float4 b = b4[c4];
                b = make_float4(b.x * inv, b.y * inv, b.z * inv, b.w * inv);
                b4[c4] = b;
                S0[(c4 * 4 + 0) * EPI_TN + nn] = a.x + b.x;
                S0[(c4 * 4 + 1) * EPI_TN + nn] = a.y + b.y;
                S0[(c4 * 4 + 2) * EPI_TN + nn] = a.z + b.z;
                S0[(c4 * 4 + 3) * EPI_TN + nn] = a.w + b.w;
                S1[(c4 * 4 + 0) * EPI_TN + nn] = a.x * b.x;
                S1[(c4 * 4 + 1) * EPI_TN + nn] = a.y * b.y;
                S1[(c4 * 4 + 2) * EPI_TN + nn] = a.z * b.z;
                S1[(c4 * 4 + 3) * EPI_TN + nn] = a.w * b.w;
            }
        } else {
            #pragma unroll
            for (int c4 = half * 8; c4 < half * 8 + 8; c4++) {
                #pragma unroll
                for (int q = 0; q < 4; q++) {
                    S0[(c4 * 4 + q) * EPI_TN + nn] = 0.f;
                    S1[(c4 * 4 + q) * EPI_TN + nn] = 0.f;
                }
            }
        }
    }
    __syncthreads();

    const int cg = tid & 7;
    const int tr = tid >> 3;
    const float* w1base = W1s + cg * 2;
    const float* w2base = W2s + cg * 2;
    const float* xb0 = S0 + tr * 4;
    const float* xb1 = S1 + tr * 4;

    unsigned long long acc1[4][4], acc2[4][4];
    #pragma unroll
    for (int m = 0; m < 4; m++)
        #pragma unroll
        for (int j = 0; j < 4; j++) { acc1[m][j] = 0ull; acc2[m][j] = 0ull; }

    #pragma unroll 4
    for (int d = 0; d < 64; d++) {
        unsigned long long w1v[4], w2v[4];
        #pragma unroll
        for (int j = 0; j < 4; j++) {
            w1v[j] = *(const unsigned long long*)(w1base + d * 64 + 16 * j);
            w2v[j] = *(const unsigned long long*)(w2base + d * 64 + 16 * j);
        }
        #pragma unroll
        for (int m = 0; m < 4; m++) {
            unsigned long long x0 = pack2(xb0[d * EPI_TN + m]);
            unsigned long long x1 = pack2(xb1[d * EPI_TN + m]);
            #pragma unroll
            for (int j = 0; j < 4; j++) {
                ffma2(acc1[m][j], x0, w1v[j]);
                ffma2(acc2[m][j], x1, w2v[j]);
            }
        }
    }

    #pragma unroll
    for (int m = 0; m < 4; m++) {
        int n = n0 + tr * 4 + m;
        if (n >= N_NODES) continue;
        float* orow = out + (size_t)n * DIM + cg * 2;
        #pragma unroll
        for (int j = 0; j < 4; j++) {
            float lo1, hi1, lo2, hi2;
            unpack2(acc1[m][j], lo1, hi1);
            unpack2(acc2[m][j], lo2, hi2);
            orow[16 * j]     = leaky(lo1) + leaky(lo2);
            orow[16 * j + 1] = leaky(hi1) + leaky(hi2);
        }
    }
}

// ---------------- launch ----------------
extern "C" void kernel_launch(void* const* d_in, const int* in_sizes, int n_in,
                              void* d_out, int out_size) {
    const float* nfeat = (const float*)d_in[0];
    const float* efeat = (const float*)d_in[1];
    const float* relW  = (const float*)d_in[2];
    const float* W1    = (const float*)d_in[3];
    const float* W2    = (const float*)d_in[4];
    const int*   src   = (const int*)d_in[5];
    const int*   dst   = (const int*)d_in[6];
    const int*   etype = (const int*)d_in[7];

    float* hnb  = (float*)d_out;
    float* out2 = (float*)d_out + (size_t)N_NODES * DIM;

    // opt-in to >48KB dynamic smem (host-side attribute; not a stream op,
    // legal during graph capture; idempotent)
    cudaFuncSetAttribute(proj_mma_kernel,
                         cudaFuncAttributeMaxDynamicSharedMemorySize, SM_TOTAL);

    const int TB = (N_NODES + 127) / 128;   // 391 tiles

    // #1, #2
    init_hnb_kernel<<<(N_NODES * DIM / 4 + 255) / 256, 256>>>(hnb);
    init_denom_kernel<<<(N_NODES + 255) / 256, 256>>>();
    // #3 (rel group 0 = relations 0..3), #4 (groups 1..3 = relations 4..15) <- ncu
    proj_mma_kernel<<<dim3(TB, 1), 256, SM_TOTAL>>>(nfeat, relW, 0);
    proj_mma_kernel<<<dim3(TB, 3), 256, SM_TOTAL>>>(nfeat, relW, 1);
    // #5
    att_fused_kernel<<<(N_EDGES / 2 * 16 + 255) / 256, 256>>>(efeat, nfeat, src, dst, etype, hnb);
    // #6
    epilogue_kernel<<<(N_NODES + EPI_TN - 1) / EPI_TN, 256>>>(nfeat, hnb, W1, W2, out2);
}

// round 17
// speedup vs baseline: 1.5641x; 1.0574x over previous
#include <cuda_runtime.h>
#include <cuda_bf16.h>
#include <cstdint>

#define N_NODES 50000
#define N_EDGES 800000
#define DIM     64
#define N_REL   16

// ---------------- scratch (device globals: allocation-free) ----------------
__device__ float g_proj[(size_t)N_REL * N_NODES * DIM];  // 204.8 MB
__device__ float g_denom[N_NODES];

// ---------------- generic helpers ----------------
__device__ __forceinline__ float fast_tanh(float x) {
    float xc = fminf(fmaxf(x, -15.f), 15.f);
    float t  = __expf(2.f * xc);
    return __fdividef(t - 1.f, t + 1.f);
}
__device__ __forceinline__ unsigned long long pack2(float x) {
    unsigned long long r;
    asm("mov.b64 %0, {%1, %1};" : "=l"(r) : "f"(x));
    return r;
}
__device__ __forceinline__ void ffma2(unsigned long long& d,
                                      unsigned long long a,
                                      unsigned long long b) {
    asm("fma.rn.f32x2 %0, %1, %2, %0;" : "+l"(d) : "l"(a), "l"(b));
}
__device__ __forceinline__ void unpack2(unsigned long long v, float& lo, float& hi) {
    asm("mov.b64 {%0, %1}, %2;" : "=f"(lo), "=f"(hi) : "l"(v));
}
__device__ __forceinline__ float leaky(float x) { return x >= 0.f ? x : 0.01f * x; }
__device__ __forceinline__ float4 ldcg4(const float4* p) {
    float4 v;
    asm volatile("ld.global.cg.v4.f32 {%0,%1,%2,%3}, [%4];"
                 : "=f"(v.x), "=f"(v.y), "=f"(v.z), "=f"(v.w) : "l"(p));
    return v;
}
__device__ __forceinline__ uint32_t smem_to_u32(const void* p) {
    uint32_t a;
    asm("{ .reg .u64 t; cvta.to.shared.u64 t, %1; cvt.u32.u64 %0, t; }"
        : "=r"(a) : "l"(p));
    return a;
}
__device__ __forceinline__ uint32_t bfpack(float a, float b) {
    __nv_bfloat16 ha = __float2bfloat16(a), hb = __float2bfloat16(b);
    return (uint32_t)__bfloat16_as_ushort(hb) << 16 | __bfloat16_as_ushort(ha);
}

// ---------------- mma.sync / ldmatrix wrappers (sm_80+ path) ----------------
__device__ __forceinline__ void mma_bf16(float c[4],
                                         const uint32_t a[4],
                                         uint32_t b0, uint32_t b1) {
    asm volatile("mma.sync.aligned.m16n8k16.row.col.f32.bf16.bf16.f32 "
                 "{%0,%1,%2,%3}, {%4,%5,%6,%7}, {%8,%9}, {%0,%1,%2,%3};"
                 : "+f"(c[0]), "+f"(c[1]), "+f"(c[2]), "+f"(c[3])
                 : "r"(a[0]), "r"(a[1]), "r"(a[2]), "r"(a[3]), "r"(b0), "r"(b1));
}
__device__ __forceinline__ void ldsm_x4(uint32_t* r, uint32_t addr) {
    asm volatile("ldmatrix.sync.aligned.m8n8.x4.shared.b16 {%0,%1,%2,%3}, [%4];"
                 : "=r"(r[0]), "=r"(r[1]), "=r"(r[2]), "=r"(r[3]) : "r"(addr));
}
__device__ __forceinline__ void ldsm_x4_t(uint32_t* r, uint32_t addr) {
    asm volatile("ldmatrix.sync.aligned.m8n8.x4.trans.shared.b16 {%0,%1,%2,%3}, [%4];"
                 : "=r"(r[0]), "=r"(r[1]), "=r"(r[2]), "=r"(r[3]) : "r"(addr));
}

// ---------------- launch #1: zero hnb ----------------
__global__ void init_hnb_kernel(float* __restrict__ hnb) {
    int i = blockIdx.x * blockDim.x + threadIdx.x;
    if (i < N_NODES * DIM / 4) ((float4*)hnb)[i] = make_float4(0.f, 0.f, 0.f, 0.f);
}
// ---------------- launch #2: zero denom ----------------
__global__ void init_denom_kernel() {
    int i = blockIdx.x * blockDim.x + threadIdx.x;
    if (i < N_NODES) g_denom[i] = 0.f;
}

// ---------------- launches #3/#4: bf16x3 proj via mma.sync, M=32/warp ------
// CTA = 256-node tile x 4 relations. Warp w owns rows w*32..w*32+31
// (2 m16 tiles), all 64 cols. B (64x64) loaded once per warp-relation now
// amortizes over 32 rows (R16: 16) -> 40% fewer L1 wavefronts per output.
#define X_LD 72
#define W_LD 72
#define TC_TN 256
#define SM_XHI 0
#define SM_XLO 36864
#define SM_WHI 73728
#define SM_WLO 82944
#define SM_TOTAL 92160

__global__ void __launch_bounds__(256, 2) proj_mma_kernel(const float* __restrict__ nfeat,
                                                          const float* __restrict__ relW,
                                                          int g_base) {
    extern __shared__ unsigned char sm[];
    uint16_t* Xhi = (uint16_t*)(sm + SM_XHI);
    uint16_t* Xlo = (uint16_t*)(sm + SM_XLO);
    uint16_t* Whi = (uint16_t*)(sm + SM_WHI);
    uint16_t* Wlo = (uint16_t*)(sm + SM_WLO);

    const int tid  = threadIdx.x;
    const int lane = tid & 31;
    const int w    = tid >> 5;                 // 0..7
    const int n0   = blockIdx.x * TC_TN;
    const int rbase = (g_base + blockIdx.y) * 4;

    // ---- X tile -> bf16 hi/lo smem (thread = one full 64-col row) ----
    {
        int n = n0 + tid;
        bool valid = (n < N_NODES);
        const float4* nr = (const float4*)(nfeat + (size_t)n * DIM);
        uint32_t* xh = (uint32_t*)&Xhi[tid * X_LD];
        uint32_t* xl = (uint32_t*)&Xlo[tid * X_LD];
        #pragma unroll
        for (int q = 0; q < 16; q++) {
            float4 v = valid ? nr[q] : make_float4(0.f, 0.f, 0.f, 0.f);
            __nv_bfloat16 h0 = __float2bfloat16(v.x), h1 = __float2bfloat16(v.y);
            __nv_bfloat16 h2 = __float2bfloat16(v.z), h3 = __float2bfloat16(v.w);
            xh[q * 2]     = (uint32_t)__bfloat16_as_ushort(h1) << 16 | __bfloat16_as_ushort(h0);
            xh[q * 2 + 1] = (uint32_t)__bfloat16_as_ushort(h3) << 16 | __bfloat16_as_ushort(h2);
            xl[q * 2]     = bfpack(v.x - __bfloat162float(h0), v.y - __bfloat162float(h1));
            xl[q * 2 + 1] = bfpack(v.z - __bfloat162float(h2), v.w - __bfloat162float(h3));
        }
    }

    // ldmatrix base addresses (lane-dependent, loop-invariant)
    uint32_t aHi0 = smem_to_u32(&Xhi[(w * 32 + (lane & 15)) * X_LD]) + (lane >> 4) * 16;
    uint32_t aLo0 = smem_to_u32(&Xlo[(w * 32 + (lane & 15)) * X_LD]) + (lane >> 4) * 16;
    uint32_t aHi1 = aHi0 + 16 * X_LD * 2;      // second m16 tile (+16 rows)
    uint32_t aLo1 = aLo0 + 16 * X_LD * 2;
    int bk = (lane & 7) + ((lane >> 3) & 1) * 8;   // k row within chunk
    int bn = (lane >> 4) * 8;                      // n sub-block
    uint32_t bHi = smem_to_u32(&Whi[bk * W_LD + bn]);
    uint32_t bLo = smem_to_u32(&Wlo[bk * W_LD + bn]);

    #pragma unroll 1
    for (int ri = 0; ri < 4; ri++) {
        const int r = rbase + ri;
        __syncthreads();   // prior ldmatrix reads done before W overwrite
        // ---- W_r -> bf16 hi/lo smem (thread: row=tid>>2, 16 cols) ----
        {
            int row = tid >> 2, q4 = tid & 3;
            const float4* wr = (const float4*)(relW + (size_t)r * 4096 + row * 64 + q4 * 16);
            uint32_t* wh = (uint32_t*)&Whi[row * W_LD + q4 * 16];
            uint32_t* wl = (uint32_t*)&Wlo[row * W_LD + q4 * 16];
            #pragma unroll
            for (int q = 0; q < 4; q++) {
                float4 v = wr[q];
                __nv_bfloat16 h0 = __float2bfloat16(v.x), h1 = __float2bfloat16(v.y);
                __nv_bfloat16 h2 = __float2bfloat16(v.z), h3 = __float2bfloat16(v.w);
                wh[q * 2]     = (uint32_t)__bfloat16_as_ushort(h1) << 16 | __bfloat16_as_ushort(h0);
                wh[q * 2 + 1] = (uint32_t)__bfloat16_as_ushort(h3) << 16 | __bfloat16_as_ushort(h2);
                wl[q * 2]     = bfpack(v.x - __bfloat162float(h0), v.y - __bfloat162float(h1));
                wl[q * 2 + 1] = bfpack(v.z - __bfloat162float(h2), v.w - __bfloat162float(h3));
            }
        }
        __syncthreads();

        float acc[2][8][4];
        #pragma unroll
        for (int m = 0; m < 2; m++)
            #pragma unroll
            for (int nt = 0; nt < 8; nt++)
                #pragma unroll
                for (int q = 0; q < 4; q++) acc[m][nt][q] = 0.f;

        #pragma unroll
        for (int kc = 0; kc < 4; kc++) {
            uint32_t ah[2][4], al[2][4];
            ldsm_x4(ah[0], aHi0 + kc * 32);
            ldsm_x4(ah[1], aHi1 + kc * 32);
            ldsm_x4(al[0], aLo0 + kc * 32);
            ldsm_x4(al[1], aLo1 + kc * 32);

            uint32_t bb[16];
            #pragma unroll
            for (int pi = 0; pi < 4; pi++)
                ldsm_x4_t(bb + pi * 4, bHi + kc * 16 * W_LD * 2 + pi * 32);
            #pragma unroll
            for (int m = 0; m < 2; m++)
                #pragma unroll
                for (int nt = 0; nt < 8; nt++) {
                    int bi = (nt >> 1) * 4 + (nt & 1) * 2;
                    mma_bf16(acc[m][nt], ah[m], bb[bi], bb[bi + 1]);
                }
            #pragma unroll
            for (int m = 0; m < 2; m++)
                #pragma unroll
                for (int nt = 0; nt < 8; nt++) {
                    int bi = (nt >> 1) * 4 + (nt & 1) * 2;
                    mma_bf16(acc[m][nt], al[m], bb[bi], bb[bi + 1]);
                }
            #pragma unroll
            for (int pi = 0; pi < 4; pi++)
                ldsm_x4_t(bb + pi * 4, bLo + kc * 16 * W_LD * 2 + pi * 32);
            #pragma unroll
            for (int m = 0; m < 2; m++)
                #pragma unroll
                for (int nt = 0; nt < 8; nt++) {
                    int bi = (nt >> 1) * 4 + (nt & 1) * 2;
                    mma_bf16(acc[m][nt], ah[m], bb[bi], bb[bi + 1]);
                }
        }

        // ---- store: rows w*32 + m*16 + (lane>>2) (+8), cols nt*8+(lane&3)*2
        float* obase = g_proj + (size_t)r * N_NODES * DIM;
        #pragma unroll
        for (int m = 0; m < 2; m++) {
            int row0 = n0 + w * 32 + m * 16 + (lane >> 2);
            #pragma unroll
            for (int nt = 0; nt < 8; nt++) {
                int col = nt * 8 + (lane & 3) * 2;
                if (row0 < N_NODES)
                    *(float2*)(obase + (size_t)row0 * DIM + col) =
                        make_float2(acc[m][nt][0], acc[m][nt][1]);
                if (row0 + 8 < N_NODES)
                    *(float2*)(obase + (size_t)(row0 + 8) * DIM + col) =
                        make_float2(acc[m][nt][2], acc[m][nt][3]);
            }
        }
    }
}

// ---------------- launch #5: att + aggregation (EXACT R14 config) ----------
__global__ void __launch_bounds__(256) att_fused_kernel(const float* __restrict__ efeat,
                                                        const float* __restrict__ nfeat,
                                                        const int* __restrict__ src,
                                                        const int* __restrict__ dst,
                                                        const int* __restrict__ etype,
                                                        float* __restrict__ hnb) {
    int gt = blockIdx.x * blockDim.x + threadIdx.x;
    int p  = gt >> 4;
    int sl = threadIdx.x & 15;
    if (p >= N_EDGES / 2) return;

    int2 s2 = ((const int2*)src)[p];
    int2 d2 = ((const int2*)dst)[p];
    int2 r2 = ((const int2*)etype)[p];
    int e0 = 2 * p, e1 = 2 * p + 1;

    float4 tv0 = ldcg4(((const float4*)(g_proj + ((size_t)r2.x * N_NODES + s2.x) * DIM)) + sl);
    float4 hv0 = ldcg4(((const float4*)(g_proj + ((size_t)r2.x * N_NODES + d2.x) * DIM)) + sl);
    float4 tv1 = ldcg4(((const float4*)(g_proj + ((size_t)r2.y * N_NODES + s2.y) * DIM)) + sl);
    float4 hv1 = ldcg4(((const float4*)(g_proj + ((size_t)r2.y * N_NODES + d2.y) * DIM)) + sl);
    float4 ev0 = __ldcs(((const float4*)(efeat + (size_t)e0 * DIM)) + sl);
    float4 ev1 = __ldcs(((const float4*)(efeat + (size_t)e1 * DIM)) + sl);

    float val0 = tv0.x * fast_tanh(hv0.x + ev0.x)
               + tv0.y * fast_tanh(hv0.y + ev0.y)
               + tv0.z * fast_tanh(hv0.z + ev0.z)
               + tv0.w * fast_tanh(hv0.w + ev0.w);
    float val1 = tv1.x * fast_tanh(hv1.x + ev1.x)
               + tv1.y * fast_tanh(hv1.y + ev1.y)
               + tv1.z * fast_tanh(hv1.z + ev1.z)
               + tv1.w * fast_tanh(hv1.w + ev1.w);

    #pragma unroll
    for (int off = 8; off; off >>= 1) {
        val0 += __shfl_xor_sync(0xffffffffu, val0, off);
        val1 += __shfl_xor_sync(0xffffffffu, val1, off);
    }

    float ex0 = __expf(val0);
    float ex1 = __expf(val1);

    if (sl == 0) {
        atomicAdd(&g_denom[d2.x], ex0);
        atomicAdd(&g_denom[d2.y], ex1);
    }
    {
        float4 v0 = ((const float4*)(nfeat + (size_t)s2.x * DIM))[sl];
        float4 v1 = ((const float4*)(nfeat + (size_t)s2.y * DIM))[sl];
        atomicAdd(((float4*)(hnb + (size_t)d2.x * DIM)) + sl,
                  make_float4(ex0 * v0.x, ex0 * v0.y, ex0 * v0.z, ex0 * v0.w));
        atomicAdd(((float4*)(hnb + (size_t)d2.y * DIM)) + sl,
                  make_float4(ex1 * v1.x, ex1 * v1.y, ex1 * v1.z, ex1 * v1.w));
    }
}

// ---------------- launch #6: epilogue v2 (EXACT R12/R14 config) ------------
#define EPI_TN 128
__global__ void __launch_bounds__(256, 2) epilogue_kernel(const float* __restrict__ nfeat,
                                                          float* __restrict__ hnb,
                                                          const float* __restrict__ W1,
                                                          const float* __restrict__ W2,
                                                          float* __restrict__ out) {
    __shared__ __align__(16) float W1s[64 * 64];
    __shared__ __align__(16) float W2s[64 * 64];
    __shared__ __align__(16) float S0[64 * EPI_TN];
    __shared__ __align__(16) float S1[64 * EPI_TN];

    const int n0  = blockIdx.x * EPI_TN;
    const int tid = threadIdx.x;

    {
        const float4* w1src = (const float4*)W1;
        const float4* w2src = (const float4*)W2;
        float4* w1dst = (float4*)W1s;
        float4* w2dst = (float4*)W2s;
        #pragma unroll
        for (int i = tid; i < 1024; i += 256) { w1dst[i] = w1src[i]; w2dst[i] = w2src[i]; }
    }
    {
        int nn   = tid & 127;
        int half = tid >> 7;
        int n    = n0 + nn;
        if (n < N_NODES) {
            float den = g_denom[n];
            float inv = (den > 0.f) ? (1.f / den) : 0.f;
            const float4* a4 = (const float4*)(nfeat + (size_t)n * DIM);
            float4*       b4 = (float4*)(hnb + (size_t)n * DIM);
            #pragma unroll
            for (int c4 = half * 8; c4 < half * 8 + 8; c4++) {
                float4 a = a4[c4];
                float4 b = b4[c4];
                b = make_float4(b.x * inv, b.y * inv, b.z * inv, b.w * inv);
                b4[c4] = b;
                S0[(c4 * 4 + 0) * EPI_TN + nn] = a.x + b.x;
                S0[(c4 * 4 + 1) * EPI_TN + nn] = a.y + b.y;
                S0[(c4 * 4 + 2) * EPI_TN + nn] = a.z + b.z;
                S0[(c4 * 4 + 3) * EPI_TN + nn] = a.w + b.w;
                S1[(c4 * 4 + 0) * EPI_TN + nn] = a.x * b.x;
                S1[(c4 * 4 + 1) * EPI_TN + nn] = a.y * b.y;
                S1[(c4 * 4 + 2) * EPI_TN + nn] = a.z * b.z;
                S1[(c4 * 4 + 3) * EPI_TN + nn] = a.w * b.w;
            }
        } else {
            #pragma unroll
            for (int c4 = half * 8; c4 < half * 8 + 8; c4++) {
                #pragma unroll
                for (int q = 0; q < 4; q++) {
                    S0[(c4 * 4 + q) * EPI_TN + nn] = 0.f;
                    S1[(c4 * 4 + q) * EPI_TN + nn] = 0.f;
                }
            }
        }
    }
    __syncthreads();

    const int cg = tid & 7;
    const int tr = tid >> 3;
    const float* w1base = W1s + cg * 2;
    const float* w2base = W2s + cg * 2;
    const float* xb0 = S0 + tr * 4;
    const float* xb1 = S1 + tr * 4;

    unsigned long long acc1[4][4], acc2[4][4];
    #pragma unroll
    for (int m = 0; m < 4; m++)
        #pragma unroll
        for (int j = 0; j < 4; j++) { acc1[m][j] = 0ull; acc2[m][j] = 0ull; }

    #pragma unroll 4
    for (int d = 0; d < 64; d++) {
        unsigned long long w1v[4], w2v[4];
        #pragma unroll
        for (int j = 0; j < 4; j++) {
            w1v[j] = *(const unsigned long long*)(w1base + d * 64 + 16 * j);
            w2v[j] = *(const unsigned long long*)(w2base + d * 64 + 16 * j);
        }
        #pragma unroll
        for (int m = 0; m < 4; m++) {
            unsigned long long x0 = pack2(xb0[d * EPI_TN + m]);
            unsigned long long x1 = pack2(xb1[d * EPI_TN + m]);
            #pragma unroll
            for (int j = 0; j < 4; j++) {
                ffma2(acc1[m][j], x0, w1v[j]);
                ffma2(acc2[m][j], x1, w2v[j]);
            }
        }
    }

    #pragma unroll
    for (int m = 0; m < 4; m++) {
        int n = n0 + tr * 4 + m;
        if (n >= N_NODES) continue;
        float* orow = out + (size_t)n * DIM + cg * 2;
        #pragma unroll
        for (int j = 0; j < 4; j++) {
            float lo1, hi1, lo2, hi2;
            unpack2(acc1[m][j], lo1, hi1);
            unpack2(acc2[m][j], lo2, hi2);
            orow[16 * j]     = leaky(lo1) + leaky(lo2);
            orow[16 * j + 1] = leaky(hi1) + leaky(hi2);
        }
    }
}

// ---------------- launch ----------------
extern "C" void kernel_launch(void* const* d_in, const int* in_sizes, int n_in,
                              void* d_out, int out_size) {
    const float* nfeat = (const float*)d_in[0];
    const float* efeat = (const float*)d_in[1];
    const float* relW  = (const float*)d_in[2];
    const float* W1    = (const float*)d_in[3];
    const float* W2    = (const float*)d_in[4];
    const int*   src   = (const int*)d_in[5];
    const int*   dst   = (const int*)d_in[6];
    const int*   etype = (const int*)d_in[7];

    float* hnb  = (float*)d_out;
    float* out2 = (float*)d_out + (size_t)N_NODES * DIM;

    cudaFuncSetAttribute(proj_mma_kernel,
                         cudaFuncAttributeMaxDynamicSharedMemorySize, SM_TOTAL);

    const int TB = (N_NODES + TC_TN - 1) / TC_TN;   // 196 tiles

    // #1, #2
    init_hnb_kernel<<<(N_NODES * DIM / 4 + 255) / 256, 256>>>(hnb);
    init_denom_kernel<<<(N_NODES + 255) / 256, 256>>>();
    // #3 (rel group 0 = relations 0..3), #4 (groups 1..3 = relations 4..15) <- ncu
    proj_mma_kernel<<<dim3(TB, 1), 256, SM_TOTAL>>>(nfeat, relW, 0);
    proj_mma_kernel<<<dim3(TB, 3), 256, SM_TOTAL>>>(nfeat, relW, 1);
    // #5
    att_fused_kernel<<<(N_EDGES / 2 * 16 + 255) / 256, 256>>>(efeat, nfeat, src, dst, etype, hnb);
    // #6
    epilogue_kernel<<<(N_NODES + EPI_TN - 1) / EPI_TN, 256>>>(nfeat, hnb, W1, W2, out2);
}